// round 13
// baseline (speedup 1.0000x reference)
#include <cuda_runtime.h>
#include <cuda_fp16.h>
#include <cstdint>

// R13: warp-specialized mma.sync flash attention.
// 384 threads: warps 0-7 consume (MMA1/softmax/dropout-apply/MMA2, BM=128),
// warps 8-11 produce (K/V staging + ALL threefry dropout masks) one tile ahead.
// One __syncthreads per tile; double-buffered K/V + mask smem.
// QK^T split fp16, P/V plain fp16. B=1, S=4096, H=16, D=64, BN=64.

#define NSEQ 4096
#define NHEAD 16

// half-element offsets in dynamic smem
#define SQHI 0
#define SQLO 8192
#define SKHI0 16384
#define SKLO0 20480
#define SV0   24576
#define SKHI1 28672
#define SKLO1 32768
#define SV1   36864
#define MBOFF 40960                 // masks: 2 x 256 uint32 (2KB)
#define SMEM_BYTES (40960 * 2 + 2048)

// ---------------- threefry2x32, key (0,42), draw = bits1 ^ bits2 ----------------
__device__ __forceinline__ void tf_g0(uint32_t& a, uint32_t& b) {
    a += b; b = __funnelshift_l(b, b, 13); b ^= a;
    a += b; b = __funnelshift_l(b, b, 15); b ^= a;
    a += b; b = __funnelshift_l(b, b, 26); b ^= a;
    a += b; b = __funnelshift_l(b, b, 6);  b ^= a;
}
__device__ __forceinline__ void tf_g1(uint32_t& a, uint32_t& b) {
    a += b; b = __funnelshift_l(b, b, 17); b ^= a;
    a += b; b = __funnelshift_l(b, b, 29); b ^= a;
    a += b; b = __funnelshift_l(b, b, 16); b ^= a;
    a += b; b = __funnelshift_l(b, b, 24); b ^= a;
}
__device__ __forceinline__ uint32_t keep_mask(uint32_t e) {
    uint32_t a = 0u;
    uint32_t b = e + 42u;
    tf_g0(a, b); a += 42u;          b += 0x1BD11BF1u;
    tf_g1(a, b); a += 0x1BD11BF0u;  b += 2u;
    tf_g0(a, b);                    b += 45u;
    tf_g1(a, b); a += 42u;          b += 0x1BD11BF4u;
    tf_g0(a, b); a += 0x1BD11BF0u;  b += 5u;
    return (((a ^ b) >> 9) < 7549747u) ? 1u : 0u;
}

// ---------------- smem swizzle: 64-half rows (128B), XOR 16B-chunk swizzle ----------------
__device__ __forceinline__ int swz(int row, int col) {
    return (row << 6) + ((((col >> 3) ^ (row & 7)) << 3) | (col & 7));
}
__device__ __forceinline__ uint32_t sptr(const void* p) {
    return (uint32_t)__cvta_generic_to_shared(p);
}
__device__ __forceinline__ void ldsm4(uint32_t& r0, uint32_t& r1, uint32_t& r2, uint32_t& r3, uint32_t a) {
    asm volatile("ldmatrix.sync.aligned.m8n8.x4.shared.b16 {%0,%1,%2,%3}, [%4];"
                 : "=r"(r0), "=r"(r1), "=r"(r2), "=r"(r3) : "r"(a));
}
__device__ __forceinline__ void ldsm4t(uint32_t& r0, uint32_t& r1, uint32_t& r2, uint32_t& r3, uint32_t a) {
    asm volatile("ldmatrix.sync.aligned.m8n8.x4.trans.shared.b16 {%0,%1,%2,%3}, [%4];"
                 : "=r"(r0), "=r"(r1), "=r"(r2), "=r"(r3) : "r"(a));
}
__device__ __forceinline__ void mma16816(float* c, const uint32_t* a, uint32_t b0, uint32_t b1) {
    asm volatile(
        "mma.sync.aligned.m16n8k16.row.col.f32.f16.f16.f32 "
        "{%0,%1,%2,%3},{%4,%5,%6,%7},{%8,%9},{%0,%1,%2,%3};"
        : "+f"(c[0]), "+f"(c[1]), "+f"(c[2]), "+f"(c[3])
        : "r"(a[0]), "r"(a[1]), "r"(a[2]), "r"(a[3]), "r"(b0), "r"(b1));
}
__device__ __forceinline__ void cvt_hilo(float x, float y, uint32_t& hi, uint32_t& lo) {
    __half2 h = __floats2half2_rn(x, y);
    float lx = x - __half2float(__low2half(h));
    float ly = y - __half2float(__high2half(h));
    __half2 l = __floats2half2_rn(lx, ly);
    hi = *reinterpret_cast<uint32_t*>(&h);
    lo = *reinterpret_cast<uint32_t*>(&l);
}
__device__ __forceinline__ uint32_t cvt_h2(float x, float y) {
    __half2 h = __floats2half2_rn(x, y);
    return *reinterpret_cast<uint32_t*>(&h);
}
__device__ __forceinline__ float ex2(float x) {
    float y;
    asm("ex2.approx.ftz.f32 %0, %1;" : "=f"(y) : "f"(x));
    return y;
}

// producer: both mask words (for consumer tids 2p, 2p+1) for key-tile starting at j0
__device__ __forceinline__ uint2 mask_words(uint32_t e0, uint32_t e1, int qd0, int j0) {
    uint32_t w0 = 0, w1 = 0;
#pragma unroll
    for (int nt = 0; nt < 8; nt++) {
        uint32_t jb = (uint32_t)(j0 + 8 * nt);
        uint32_t j00 = jb + 2 * qd0;        // qd for consumer 2p   (even)
        uint32_t j10 = jb + 2 * qd0 + 2;    // qd for consumer 2p+1 (odd = qd0+1)
        w0 |= keep_mask(e0 + j00)      << (4 * nt);
        w0 |= keep_mask(e0 + j00 + 1u) << (4 * nt + 1);
        w0 |= keep_mask(e1 + j00)      << (4 * nt + 2);
        w0 |= keep_mask(e1 + j00 + 1u) << (4 * nt + 3);
        w1 |= keep_mask(e0 + j10)      << (4 * nt);
        w1 |= keep_mask(e0 + j10 + 1u) << (4 * nt + 1);
        w1 |= keep_mask(e1 + j10)      << (4 * nt + 2);
        w1 |= keep_mask(e1 + j10 + 1u) << (4 * nt + 3);
    }
    return make_uint2(w0, w1);
}

__global__ void __launch_bounds__(384, 1)
attn_mma(const float* __restrict__ q, const float* __restrict__ k,
         const float* __restrict__ v, float* __restrict__ out)
{
    extern __shared__ __align__(16) __half SH[];
    uint32_t* MB = reinterpret_cast<uint32_t*>(SH + MBOFF);

    const int tid = threadIdx.x;
    const int h = blockIdx.y;
    const int iBase = blockIdx.x * 128;

    if (tid < 256) {
        // ======================= CONSUMER (warps 0-7) =======================
        const int wid = tid >> 5;
        const int lane = tid & 31;
        const int qd = lane & 3;

        // stage Q (fp32 -> fp16 hi/lo) into persistent smem
#pragma unroll
        for (int it = 0; it < 8; it++) {
            int pos = tid + it * 256;
            int row = pos >> 4;
            int c4 = pos & 15;
            float4 g = *reinterpret_cast<const float4*>(q + (size_t)(iBase + row) * 1024 + h * 64 + c4 * 4);
            uint32_t h0, l0, h1, l1;
            cvt_hilo(g.x, g.y, h0, l0);
            cvt_hilo(g.z, g.w, h1, l1);
            int idx = swz(row, c4 * 4);
            *reinterpret_cast<uint2*>(&SH[SQHI + idx]) = make_uint2(h0, h1);
            *reinterpret_cast<uint2*>(&SH[SQLO + idx]) = make_uint2(l0, l1);
        }

        float o[8][4];
#pragma unroll
        for (int nt = 0; nt < 8; nt++)
#pragma unroll
            for (int c = 0; c < 4; c++) o[nt][c] = 0.0f;
        float lp0 = 0.0f, lp1 = 0.0f;

        const int n0 = iBase + 16 * wid + (lane >> 2);
        const float C = 0.18033688011112042f;   // 0.125 * log2(e)
        const int qrow = 16 * wid + (lane & 15);
        const int qcsel = (lane >> 4) << 3;

        __syncthreads();   // [A] Q staging + producer tile0 visible

        // hoist Q fragments into registers (held for all 64 tiles)
        uint32_t qh[4][4], ql[4][4];
#pragma unroll
        for (int kk = 0; kk < 4; kk++) {
            int c = kk * 16 + qcsel;
            ldsm4(qh[kk][0], qh[kk][1], qh[kk][2], qh[kk][3], sptr(&SH[SQHI + swz(qrow, c)]));
            ldsm4(ql[kk][0], ql[kk][1], ql[kk][2], ql[kk][3], sptr(&SH[SQLO + swz(qrow, c)]));
        }

        for (int t = 0; t < 64; t++) {
            __syncthreads();   // [B(t)] tile t buffers + masks visible
            const int rb = t & 1;
            const uint32_t mask = MB[rb * 256 + tid];
            const __half* Khi = SH + (rb ? SKHI1 : SKHI0);
            const __half* Klo = SH + (rb ? SKLO1 : SKLO0);
            const __half* Vs  = SH + (rb ? SV1 : SV0);

            // MMA1: S = Q K^T (split fp16: qh*kh + qh*kl + ql*kh)
            float s[8][4];
#pragma unroll
            for (int nt = 0; nt < 8; nt++)
#pragma unroll
                for (int c = 0; c < 4; c++) s[nt][c] = 0.0f;
#pragma unroll
            for (int kp = 0; kp < 2; kp++) {
#pragma unroll
                for (int nt = 0; nt < 8; nt++) {
                    int brow = 8 * nt + (lane & 7);
                    int bcol = 32 * kp + (lane & 24);
                    uint32_t bh0, bh1, bh2, bh3, bl0, bl1, bl2, bl3;
                    ldsm4(bh0, bh1, bh2, bh3, sptr(&Khi[swz(brow, bcol)]));
                    ldsm4(bl0, bl1, bl2, bl3, sptr(&Klo[swz(brow, bcol)]));
                    mma16816(s[nt], qh[2 * kp], bh0, bh1);
                    mma16816(s[nt], qh[2 * kp], bl0, bl1);
                    mma16816(s[nt], ql[2 * kp], bh0, bh1);
                    mma16816(s[nt], qh[2 * kp + 1], bh2, bh3);
                    mma16816(s[nt], qh[2 * kp + 1], bl2, bl3);
                    mma16816(s[nt], ql[2 * kp + 1], bh2, bh3);
                }
            }

            // epilogue: exp, apply producer mask bits, pack P (plain fp16)
            uint32_t ah[4][4];
#pragma unroll
            for (int nt = 0; nt < 8; nt++) {
                float p00 = ex2(s[nt][0] * C);
                float p01 = ex2(s[nt][1] * C);
                float p10 = ex2(s[nt][2] * C);
                float p11 = ex2(s[nt][3] * C);
                lp0 += p00 + p01;
                lp1 += p10 + p11;
                if (!((mask >> (4 * nt)) & 1u))     p00 = 0.0f;
                if (!((mask >> (4 * nt + 1)) & 1u)) p01 = 0.0f;
                if (!((mask >> (4 * nt + 2)) & 1u)) p10 = 0.0f;
                if (!((mask >> (4 * nt + 3)) & 1u)) p11 = 0.0f;
                int kk2 = nt >> 1, sel = (nt & 1) * 2;
                ah[kk2][sel + 0] = cvt_h2(p00, p01);
                ah[kk2][sel + 1] = cvt_h2(p10, p11);
            }

            // MMA2: O += P V (both plain fp16)
#pragma unroll
            for (int nt = 0; nt < 8; nt++) {
                int bcol = 8 * nt;
#pragma unroll
                for (int kp = 0; kp < 2; kp++) {
                    int brow = 32 * kp + lane;
                    uint32_t vh0, vh1, vh2, vh3;
                    ldsm4t(vh0, vh1, vh2, vh3, sptr(&Vs[swz(brow, bcol)]));
                    mma16816(o[nt], ah[2 * kp], vh0, vh1);
                    mma16816(o[nt], ah[2 * kp + 1], vh2, vh3);
                }
            }
        }

        // row-sum reduction within each quad, then scatter
        lp0 += __shfl_xor_sync(0xffffffffu, lp0, 1);
        lp0 += __shfl_xor_sync(0xffffffffu, lp0, 2);
        lp1 += __shfl_xor_sync(0xffffffffu, lp1, 1);
        lp1 += __shfl_xor_sync(0xffffffffu, lp1, 2);
        const float inv0 = 1.0f / (lp0 * 0.9f);
        const float inv1 = 1.0f / (lp1 * 0.9f);

        const int n1 = n0 + 8;
        float* ob0 = out + (size_t)((n0 & 255) * 16 + h) * 1024 + (n0 >> 8) * 64;
        float* ob1 = out + (size_t)((n1 & 255) * 16 + h) * 1024 + (n1 >> 8) * 64;
#pragma unroll
        for (int nt = 0; nt < 8; nt++) {
            int dv = 8 * nt + 2 * qd;
            *reinterpret_cast<float2*>(ob0 + dv) = make_float2(o[nt][0] * inv0, o[nt][1] * inv0);
            *reinterpret_cast<float2*>(ob1 + dv) = make_float2(o[nt][2] * inv1, o[nt][3] * inv1);
        }
    } else {
        // ======================= PRODUCER (warps 8-11) =======================
        const int ptid = tid - 256;             // 0..127
        const int srow = ptid >> 1;             // 0..63
        const int fc = (ptid & 1) << 3;         // float4 col base: 0 or 8
        const size_t gbase = (size_t)srow * 1024 + h * 64 + fc * 4;

        // geometry of the two consumer threads this lane serves (c0 = 2p, c1 = 2p+1)
        const int c0 = 2 * ptid;
        const int lane_c = c0 & 31;
        const int widc = c0 >> 5;
        const int n0c = iBase + 16 * widc + (lane_c >> 2);
        const uint32_t e0 = ((uint32_t)h << 24) | ((uint32_t)n0c << 12);
        const uint32_t e1 = e0 + (8u << 12);
        const int qd0 = c0 & 3;                 // even; consumer c1 has qd0+1

        float4 kf[8], vf[8];

        // ---- prologue: tile 0 -> buf0 + MB0 ----
#pragma unroll
        for (int m = 0; m < 8; m++) {
            kf[m] = *reinterpret_cast<const float4*>(k + gbase + m * 4);
            vf[m] = *reinterpret_cast<const float4*>(v + gbase + m * 4);
        }
        {
            uint2 w = mask_words(e0, e1, qd0, 0);
            *reinterpret_cast<uint2*>(&MB[2 * ptid]) = w;
#pragma unroll
            for (int m = 0; m < 8; m++) {
                uint32_t h0, l0, h1, l1;
                cvt_hilo(kf[m].x, kf[m].y, h0, l0);
                cvt_hilo(kf[m].z, kf[m].w, h1, l1);
                int idx = swz(srow, (fc + m) * 4);
                *reinterpret_cast<uint2*>(&SH[SKHI0 + idx]) = make_uint2(h0, h1);
                *reinterpret_cast<uint2*>(&SH[SKLO0 + idx]) = make_uint2(l0, l1);
                *reinterpret_cast<uint2*>(&SH[SV0 + idx]) =
                    make_uint2(cvt_h2(vf[m].x, vf[m].y), cvt_h2(vf[m].z, vf[m].w));
            }
        }

        __syncthreads();   // [A]

        for (int t = 0; t < 64; t++) {
            __syncthreads();   // [B(t)]
            const int wb = (t + 1) & 1;
            const int tn = (t < 63) ? t + 1 : 63;   // clamped; t=63 write unread
            const size_t go = (size_t)tn * 64 * 1024 + gbase;

            // loads first (latency hidden by the mask block)
#pragma unroll
            for (int m = 0; m < 8; m++) {
                kf[m] = *reinterpret_cast<const float4*>(k + go + m * 4);
                vf[m] = *reinterpret_cast<const float4*>(v + go + m * 4);
            }

            uint2 w = mask_words(e0, e1, qd0, tn * 64);
            *reinterpret_cast<uint2*>(&MB[wb * 256 + 2 * ptid]) = w;

            const int skhi_w = wb ? SKHI1 : SKHI0;
            const int sklo_w = wb ? SKLO1 : SKLO0;
            const int sv_w   = wb ? SV1 : SV0;
#pragma unroll
            for (int m = 0; m < 8; m++) {
                uint32_t h0, l0, h1, l1;
                cvt_hilo(kf[m].x, kf[m].y, h0, l0);
                cvt_hilo(kf[m].z, kf[m].w, h1, l1);
                int idx = swz(srow, (fc + m) * 4);
                *reinterpret_cast<uint2*>(&SH[skhi_w + idx]) = make_uint2(h0, h1);
                *reinterpret_cast<uint2*>(&SH[sklo_w + idx]) = make_uint2(l0, l1);
                *reinterpret_cast<uint2*>(&SH[sv_w + idx]) =
                    make_uint2(cvt_h2(vf[m].x, vf[m].y), cvt_h2(vf[m].z, vf[m].w));
            }
        }
    }
}

extern "C" void kernel_launch(void* const* d_in, const int* in_sizes, int n_in,
                              void* d_out, int out_size)
{
    const float* q = (const float*)d_in[0];
    const float* k = (const float*)d_in[1];
    const float* v = (const float*)d_in[2];
    float* out = (float*)d_out;
    cudaFuncSetAttribute(attn_mma, cudaFuncAttributeMaxDynamicSharedMemorySize, SMEM_BYTES);
    dim3 grid(NSEQ / 128, NHEAD);
    attn_mma<<<grid, 384, SMEM_BYTES>>>(q, k, v, out);
}

// round 14
// speedup vs baseline: 1.2829x; 1.2829x over previous
#include <cuda_runtime.h>
#include <cuda_fp16.h>
#include <cstdint>

// R14: R12 structure, register cap REMOVED (1 CTA/SM, regs float) so the
// 32-chain threefry batch keeps full ILP. P/V plain fp16, QK^T split fp16,
// double-buffered K/V, one __syncthreads per tile, batched masks.
// B=1, S=4096, H=16, D=64. BM=128 (8 warps x 16 rows), BN=64 keys/tile.

#define NSEQ 4096
#define NHEAD 16

// half-element offsets in dynamic smem (80KB total)
#define SQHI 0
#define SQLO 8192
#define SKHI0 16384
#define SKLO0 20480
#define SV0   24576
#define SKHI1 28672
#define SKLO1 32768
#define SV1   36864
#define SMEM_BYTES (40960 * 2)

// ---------------- threefry2x32, key (0,42), draw = bits1 ^ bits2 ----------------
__device__ __forceinline__ void tf_g0(uint32_t& a, uint32_t& b) {
    a += b; b = __funnelshift_l(b, b, 13); b ^= a;
    a += b; b = __funnelshift_l(b, b, 15); b ^= a;
    a += b; b = __funnelshift_l(b, b, 26); b ^= a;
    a += b; b = __funnelshift_l(b, b, 6);  b ^= a;
}
__device__ __forceinline__ void tf_g1(uint32_t& a, uint32_t& b) {
    a += b; b = __funnelshift_l(b, b, 17); b ^= a;
    a += b; b = __funnelshift_l(b, b, 29); b ^= a;
    a += b; b = __funnelshift_l(b, b, 16); b ^= a;
    a += b; b = __funnelshift_l(b, b, 24); b ^= a;
}
__device__ __forceinline__ uint32_t keep_mask(uint32_t e) {
    uint32_t a = 0u;
    uint32_t b = e + 42u;
    tf_g0(a, b); a += 42u;          b += 0x1BD11BF1u;
    tf_g1(a, b); a += 0x1BD11BF0u;  b += 2u;
    tf_g0(a, b);                    b += 45u;
    tf_g1(a, b); a += 42u;          b += 0x1BD11BF4u;
    tf_g0(a, b); a += 0x1BD11BF0u;  b += 5u;
    // (x>>9) < 7549747  <=>  x < 7549747*512 (saves the SHF)
    return ((a ^ b) < 3865470464u) ? 1u : 0u;
}

// ---------------- smem swizzle: 64-half rows (128B), XOR 16B-chunk swizzle ----------------
__device__ __forceinline__ int swz(int row, int col) {
    return (row << 6) + ((((col >> 3) ^ (row & 7)) << 3) | (col & 7));
}
__device__ __forceinline__ uint32_t sptr(const void* p) {
    return (uint32_t)__cvta_generic_to_shared(p);
}
__device__ __forceinline__ void ldsm4(uint32_t& r0, uint32_t& r1, uint32_t& r2, uint32_t& r3, uint32_t a) {
    asm volatile("ldmatrix.sync.aligned.m8n8.x4.shared.b16 {%0,%1,%2,%3}, [%4];"
                 : "=r"(r0), "=r"(r1), "=r"(r2), "=r"(r3) : "r"(a));
}
__device__ __forceinline__ void ldsm4t(uint32_t& r0, uint32_t& r1, uint32_t& r2, uint32_t& r3, uint32_t a) {
    asm volatile("ldmatrix.sync.aligned.m8n8.x4.trans.shared.b16 {%0,%1,%2,%3}, [%4];"
                 : "=r"(r0), "=r"(r1), "=r"(r2), "=r"(r3) : "r"(a));
}
__device__ __forceinline__ void mma16816(float* c, const uint32_t* a, uint32_t b0, uint32_t b1) {
    asm volatile(
        "mma.sync.aligned.m16n8k16.row.col.f32.f16.f16.f32 "
        "{%0,%1,%2,%3},{%4,%5,%6,%7},{%8,%9},{%0,%1,%2,%3};"
        : "+f"(c[0]), "+f"(c[1]), "+f"(c[2]), "+f"(c[3])
        : "r"(a[0]), "r"(a[1]), "r"(a[2]), "r"(a[3]), "r"(b0), "r"(b1));
}
__device__ __forceinline__ void cvt_hilo(float x, float y, uint32_t& hi, uint32_t& lo) {
    __half2 h = __floats2half2_rn(x, y);
    float lx = x - __half2float(__low2half(h));
    float ly = y - __half2float(__high2half(h));
    __half2 l = __floats2half2_rn(lx, ly);
    hi = *reinterpret_cast<uint32_t*>(&h);
    lo = *reinterpret_cast<uint32_t*>(&l);
}
__device__ __forceinline__ uint32_t cvt_h2(float x, float y) {
    __half2 h = __floats2half2_rn(x, y);
    return *reinterpret_cast<uint32_t*>(&h);
}
__device__ __forceinline__ float ex2(float x) {
    float y;
    asm("ex2.approx.ftz.f32 %0, %1;" : "=f"(y) : "f"(x));
    return y;
}

__global__ void __launch_bounds__(256, 1)
attn_mma(const float* __restrict__ q, const float* __restrict__ k,
         const float* __restrict__ v, float* __restrict__ out)
{
    extern __shared__ __align__(16) __half SH[];

    const int tid = threadIdx.x;
    const int wid = tid >> 5;
    const int lane = tid & 31;
    const int qd = lane & 3;
    const int h = blockIdx.y;
    const int iBase = blockIdx.x * 128;

    // staging geometry: thread owns row (tid>>2), float4 cols {c4..c4+3}
    const int srow = tid >> 2;              // 0..63
    const int sc4 = (tid & 3) << 2;         // float4 col base: 0,4,8,12
    const size_t gbase = (size_t)srow * 1024 + h * 64 + sc4 * 4;

    // ---- stage Q (fp32 -> fp16 hi/lo) into dedicated smem (persistent) ----
#pragma unroll
    for (int it = 0; it < 8; it++) {
        int pos = tid + it * 256;
        int row = pos >> 4;
        int c4 = pos & 15;
        float4 g = *reinterpret_cast<const float4*>(q + (size_t)(iBase + row) * 1024 + h * 64 + c4 * 4);
        uint32_t h0, l0, h1, l1;
        cvt_hilo(g.x, g.y, h0, l0);
        cvt_hilo(g.z, g.w, h1, l1);
        int idx = swz(row, c4 * 4);
        *reinterpret_cast<uint2*>(&SH[SQHI + idx]) = make_uint2(h0, h1);
        *reinterpret_cast<uint2*>(&SH[SQLO + idx]) = make_uint2(l0, l1);
    }

    // prefetch registers (converted to fp16 right after load)
    uint32_t khi[8], klo[8], vh[8];

    // ---- prologue: load+convert tile 0 ----
#pragma unroll
    for (int m = 0; m < 4; m++) {
        float4 kf = *reinterpret_cast<const float4*>(k + gbase + m * 4);
        float4 vf = *reinterpret_cast<const float4*>(v + gbase + m * 4);
        cvt_hilo(kf.x, kf.y, khi[2 * m], klo[2 * m]);
        cvt_hilo(kf.z, kf.w, khi[2 * m + 1], klo[2 * m + 1]);
        vh[2 * m] = cvt_h2(vf.x, vf.y);
        vh[2 * m + 1] = cvt_h2(vf.z, vf.w);
    }

    float o[8][4];
#pragma unroll
    for (int nt = 0; nt < 8; nt++)
#pragma unroll
        for (int c = 0; c < 4; c++) o[nt][c] = 0.0f;
    float lp0 = 0.0f, lp1 = 0.0f;

    const int n0 = iBase + 16 * wid + (lane >> 2);
    const uint32_t eb0 = ((uint32_t)h << 24) | ((uint32_t)n0 << 12);
    const uint32_t eb1 = eb0 + (8u << 12);
    const float C = 0.18033688011112042f;   // 0.125 * log2(e)
    const int qrow = 16 * wid + (lane & 15);
    const int qcsel = (lane >> 4) << 3;

    __syncthreads();   // Q staging visible

    // hoist Q fragments into registers (held for all 64 tiles)
    uint32_t qh[4][4], ql[4][4];
#pragma unroll
    for (int kk = 0; kk < 4; kk++) {
        int c = kk * 16 + qcsel;
        ldsm4(qh[kk][0], qh[kk][1], qh[kk][2], qh[kk][3], sptr(&SH[SQHI + swz(qrow, c)]));
        ldsm4(ql[kk][0], ql[kk][1], ql[kk][2], ql[kk][3], sptr(&SH[SQLO + swz(qrow, c)]));
    }

    // store tile 0 into buf0
#pragma unroll
    for (int m = 0; m < 4; m++) {
        int idx = swz(srow, (sc4 + m) * 4);
        *reinterpret_cast<uint2*>(&SH[SKHI0 + idx]) = make_uint2(khi[2 * m], khi[2 * m + 1]);
        *reinterpret_cast<uint2*>(&SH[SKLO0 + idx]) = make_uint2(klo[2 * m], klo[2 * m + 1]);
        *reinterpret_cast<uint2*>(&SH[SV0 + idx])   = make_uint2(vh[2 * m], vh[2 * m + 1]);
    }

    for (int t = 0; t < 64; t++) {
        const int j0 = t * 64;
        const int rb = t & 1, wb = (t + 1) & 1;

        // ---- load+convert tile t+1 into regs (latency hidden by mask block) ----
        {
            const int tn = (t < 63) ? t + 1 : 63;
            const size_t go = (size_t)tn * 64 * 1024 + gbase;
#pragma unroll
            for (int m = 0; m < 4; m++) {
                float4 kf = *reinterpret_cast<const float4*>(k + go + m * 4);
                float4 vf = *reinterpret_cast<const float4*>(v + go + m * 4);
                cvt_hilo(kf.x, kf.y, khi[2 * m], klo[2 * m]);
                cvt_hilo(kf.z, kf.w, khi[2 * m + 1], klo[2 * m + 1]);
                vh[2 * m] = cvt_h2(vf.x, vf.y);
                vh[2 * m + 1] = cvt_h2(vf.z, vf.w);
            }
        }

        // ---- dropout masks for tile t: 32 independent threefry chains ----
        uint32_t mask = 0;
#pragma unroll
        for (int nt = 0; nt < 8; nt++) {
            uint32_t jb = (uint32_t)(j0 + 8 * nt + 2 * qd);
            mask |= keep_mask(eb0 + jb)      << (4 * nt);
            mask |= keep_mask(eb0 + jb + 1u) << (4 * nt + 1);
            mask |= keep_mask(eb1 + jb)      << (4 * nt + 2);
            mask |= keep_mask(eb1 + jb + 1u) << (4 * nt + 3);
        }

        __syncthreads();   // buf[rb] stores visible; reads(t-1) of buf[wb] done

        // ---- store tile t+1 into buf[wb] ----
        {
            const int skhi_w = wb ? SKHI1 : SKHI0;
            const int sklo_w = wb ? SKLO1 : SKLO0;
            const int sv_w   = wb ? SV1 : SV0;
#pragma unroll
            for (int m = 0; m < 4; m++) {
                int idx = swz(srow, (sc4 + m) * 4);
                *reinterpret_cast<uint2*>(&SH[skhi_w + idx]) = make_uint2(khi[2 * m], khi[2 * m + 1]);
                *reinterpret_cast<uint2*>(&SH[sklo_w + idx]) = make_uint2(klo[2 * m], klo[2 * m + 1]);
                *reinterpret_cast<uint2*>(&SH[sv_w + idx])   = make_uint2(vh[2 * m], vh[2 * m + 1]);
            }
        }

        const __half* Khi = SH + (rb ? SKHI1 : SKHI0);
        const __half* Klo = SH + (rb ? SKLO1 : SKLO0);
        const __half* Vs  = SH + (rb ? SV1 : SV0);

        // ---- MMA1: S = Q K^T (split fp16: qh*kh + qh*kl + ql*kh) ----
        float s[8][4];
#pragma unroll
        for (int nt = 0; nt < 8; nt++)
#pragma unroll
            for (int c = 0; c < 4; c++) s[nt][c] = 0.0f;

#pragma unroll
        for (int kp = 0; kp < 2; kp++) {
#pragma unroll
            for (int nt = 0; nt < 8; nt++) {
                int brow = 8 * nt + (lane & 7);
                int bcol = 32 * kp + (lane & 24);
                uint32_t bh0, bh1, bh2, bh3, bl0, bl1, bl2, bl3;
                ldsm4(bh0, bh1, bh2, bh3, sptr(&Khi[swz(brow, bcol)]));
                ldsm4(bl0, bl1, bl2, bl3, sptr(&Klo[swz(brow, bcol)]));
                mma16816(s[nt], qh[2 * kp], bh0, bh1);
                mma16816(s[nt], qh[2 * kp], bl0, bl1);
                mma16816(s[nt], ql[2 * kp], bh0, bh1);
                mma16816(s[nt], qh[2 * kp + 1], bh2, bh3);
                mma16816(s[nt], qh[2 * kp + 1], bl2, bl3);
                mma16816(s[nt], ql[2 * kp + 1], bh2, bh3);
            }
        }

        // ---- epilogue: exp, apply mask, pack P to plain fp16 A-frags ----
        uint32_t ah[4][4];
#pragma unroll
        for (int nt = 0; nt < 8; nt++) {
            float p00 = ex2(s[nt][0] * C);
            float p01 = ex2(s[nt][1] * C);
            float p10 = ex2(s[nt][2] * C);
            float p11 = ex2(s[nt][3] * C);
            lp0 += p00 + p01;
            lp1 += p10 + p11;
            if (!((mask >> (4 * nt)) & 1u))     p00 = 0.0f;
            if (!((mask >> (4 * nt + 1)) & 1u)) p01 = 0.0f;
            if (!((mask >> (4 * nt + 2)) & 1u)) p10 = 0.0f;
            if (!((mask >> (4 * nt + 3)) & 1u)) p11 = 0.0f;
            int kk2 = nt >> 1, sel = (nt & 1) * 2;
            ah[kk2][sel + 0] = cvt_h2(p00, p01);
            ah[kk2][sel + 1] = cvt_h2(p10, p11);
        }

        // ---- MMA2: O += P V (both plain fp16) ----
#pragma unroll
        for (int nt = 0; nt < 8; nt++) {
            int bcol = 8 * nt;
#pragma unroll
            for (int kp = 0; kp < 2; kp++) {
                int brow = 32 * kp + lane;
                uint32_t vh0, vh1, vh2, vh3;
                ldsm4t(vh0, vh1, vh2, vh3, sptr(&Vs[swz(brow, bcol)]));
                mma16816(o[nt], ah[2 * kp], vh0, vh1);
                mma16816(o[nt], ah[2 * kp + 1], vh2, vh3);
            }
        }
    }

    // row-sum reduction within each quad (same row, 4 threads over columns)
    lp0 += __shfl_xor_sync(0xffffffffu, lp0, 1);
    lp0 += __shfl_xor_sync(0xffffffffu, lp0, 2);
    lp1 += __shfl_xor_sync(0xffffffffu, lp1, 1);
    lp1 += __shfl_xor_sync(0xffffffffu, lp1, 2);
    const float inv0 = 1.0f / (lp0 * 0.9f);
    const float inv1 = 1.0f / (lp1 * 0.9f);

    // scatter per reference reshape chain: out[((n&255)*16+h)*1024 + (n>>8)*64 + dv]
    const int n1 = n0 + 8;
    float* ob0 = out + (size_t)((n0 & 255) * 16 + h) * 1024 + (n0 >> 8) * 64;
    float* ob1 = out + (size_t)((n1 & 255) * 16 + h) * 1024 + (n1 >> 8) * 64;
#pragma unroll
    for (int nt = 0; nt < 8; nt++) {
        int dv = 8 * nt + 2 * qd;
        *reinterpret_cast<float2*>(ob0 + dv) = make_float2(o[nt][0] * inv0, o[nt][1] * inv0);
        *reinterpret_cast<float2*>(ob1 + dv) = make_float2(o[nt][2] * inv1, o[nt][3] * inv1);
    }
}

extern "C" void kernel_launch(void* const* d_in, const int* in_sizes, int n_in,
                              void* d_out, int out_size)
{
    const float* q = (const float*)d_in[0];
    const float* k = (const float*)d_in[1];
    const float* v = (const float*)d_in[2];
    float* out = (float*)d_out;
    cudaFuncSetAttribute(attn_mma, cudaFuncAttributeMaxDynamicSharedMemorySize, SMEM_BYTES);
    dim3 grid(NSEQ / 128, NHEAD);
    attn_mma<<<grid, 256, SMEM_BYTES>>>(q, k, v, out);
}

// round 15
// speedup vs baseline: 1.3840x; 1.0788x over previous
#include <cuda_runtime.h>
#include <cuda_fp16.h>
#include <cstdint>

// R15 = R8 structure exactly (2 CTAs/SM, single-buffer K/V, 2 syncs/tile,
// Q-frags reloaded from smem, batched threefry) with ONLY:
//   - V plain fp16 (Vlo dropped), P plain fp16 (MMA2 96->32 HMMA)
//   - folded mask compare (x < 7549747*512), bit-exact
// B=1, S=4096, H=16, D=64. BM=128 (8 warps x 16 rows), BN=64 keys/tile.

#define NSEQ 4096
#define NHEAD 16

// half-element offsets in dynamic smem (56KB total)
#define SQHI 0
#define SQLO 8192
#define SKHI 16384
#define SKLO 20480
#define SV   24576
#define SMEM_BYTES (28672 * 2)

// ---------------- threefry2x32, key (0,42), draw = bits1 ^ bits2 ----------------
__device__ __forceinline__ void tf_g0(uint32_t& a, uint32_t& b) {
    a += b; b = __funnelshift_l(b, b, 13); b ^= a;
    a += b; b = __funnelshift_l(b, b, 15); b ^= a;
    a += b; b = __funnelshift_l(b, b, 26); b ^= a;
    a += b; b = __funnelshift_l(b, b, 6);  b ^= a;
}
__device__ __forceinline__ void tf_g1(uint32_t& a, uint32_t& b) {
    a += b; b = __funnelshift_l(b, b, 17); b ^= a;
    a += b; b = __funnelshift_l(b, b, 29); b ^= a;
    a += b; b = __funnelshift_l(b, b, 16); b ^= a;
    a += b; b = __funnelshift_l(b, b, 24); b ^= a;
}
__device__ __forceinline__ uint32_t keep_mask(uint32_t e) {
    uint32_t a = 0u;
    uint32_t b = e + 42u;
    tf_g0(a, b); a += 42u;          b += 0x1BD11BF1u;
    tf_g1(a, b); a += 0x1BD11BF0u;  b += 2u;
    tf_g0(a, b);                    b += 45u;
    tf_g1(a, b); a += 42u;          b += 0x1BD11BF4u;
    tf_g0(a, b); a += 0x1BD11BF0u;  b += 5u;
    // (x>>9) < 7549747  <=>  x < 7549747*512 (bit-exact, saves the SHF)
    return ((a ^ b) < 3865470464u) ? 1u : 0u;
}

// ---------------- smem swizzle: 64-half rows (128B), XOR 16B-chunk swizzle ----------------
__device__ __forceinline__ int swz(int row, int col) {
    return (row << 6) + ((((col >> 3) ^ (row & 7)) << 3) | (col & 7));
}
__device__ __forceinline__ uint32_t sptr(const void* p) {
    return (uint32_t)__cvta_generic_to_shared(p);
}
__device__ __forceinline__ void ldsm4(uint32_t& r0, uint32_t& r1, uint32_t& r2, uint32_t& r3, uint32_t a) {
    asm volatile("ldmatrix.sync.aligned.m8n8.x4.shared.b16 {%0,%1,%2,%3}, [%4];"
                 : "=r"(r0), "=r"(r1), "=r"(r2), "=r"(r3) : "r"(a));
}
__device__ __forceinline__ void ldsm4t(uint32_t& r0, uint32_t& r1, uint32_t& r2, uint32_t& r3, uint32_t a) {
    asm volatile("ldmatrix.sync.aligned.m8n8.x4.trans.shared.b16 {%0,%1,%2,%3}, [%4];"
                 : "=r"(r0), "=r"(r1), "=r"(r2), "=r"(r3) : "r"(a));
}
__device__ __forceinline__ void mma16816(float* c, const uint32_t* a, uint32_t b0, uint32_t b1) {
    asm volatile(
        "mma.sync.aligned.m16n8k16.row.col.f32.f16.f16.f32 "
        "{%0,%1,%2,%3},{%4,%5,%6,%7},{%8,%9},{%0,%1,%2,%3};"
        : "+f"(c[0]), "+f"(c[1]), "+f"(c[2]), "+f"(c[3])
        : "r"(a[0]), "r"(a[1]), "r"(a[2]), "r"(a[3]), "r"(b0), "r"(b1));
}
__device__ __forceinline__ void cvt_hilo(float x, float y, uint32_t& hi, uint32_t& lo) {
    __half2 h = __floats2half2_rn(x, y);
    float lx = x - __half2float(__low2half(h));
    float ly = y - __half2float(__high2half(h));
    __half2 l = __floats2half2_rn(lx, ly);
    hi = *reinterpret_cast<uint32_t*>(&h);
    lo = *reinterpret_cast<uint32_t*>(&l);
}
__device__ __forceinline__ uint32_t cvt_h2(float x, float y) {
    __half2 h = __floats2half2_rn(x, y);
    return *reinterpret_cast<uint32_t*>(&h);
}
__device__ __forceinline__ float ex2(float x) {
    float y;
    asm("ex2.approx.ftz.f32 %0, %1;" : "=f"(y) : "f"(x));
    return y;
}

__global__ void __launch_bounds__(256, 2)
attn_mma(const float* __restrict__ q, const float* __restrict__ k,
         const float* __restrict__ v, float* __restrict__ out)
{
    extern __shared__ __align__(16) __half SH[];
    __half* Khi = SH + SKHI;
    __half* Klo = SH + SKLO;
    __half* Vs  = SH + SV;

    const int tid = threadIdx.x;
    const int wid = tid >> 5;
    const int lane = tid & 31;
    const int qd = lane & 3;
    const int h = blockIdx.y;
    const int iBase = blockIdx.x * 128;

    // ---- stage Q (fp32 -> fp16 hi/lo) into dedicated smem (persistent) ----
#pragma unroll
    for (int it = 0; it < 8; it++) {
        int pos = tid + it * 256;          // 0..2047 float4s
        int row = pos >> 4;                // 0..127
        int c4 = pos & 15;
        float4 g = *reinterpret_cast<const float4*>(q + (size_t)(iBase + row) * 1024 + h * 64 + c4 * 4);
        uint32_t h0, l0, h1, l1;
        cvt_hilo(g.x, g.y, h0, l0);
        cvt_hilo(g.z, g.w, h1, l1);
        int idx = swz(row, c4 * 4);
        *reinterpret_cast<uint2*>(&SH[SQHI + idx]) = make_uint2(h0, h1);
        *reinterpret_cast<uint2*>(&SH[SQLO + idx]) = make_uint2(l0, l1);
    }

    float o[8][4];
#pragma unroll
    for (int nt = 0; nt < 8; nt++)
#pragma unroll
        for (int c = 0; c < 4; c++) o[nt][c] = 0.0f;
    float lp0 = 0.0f, lp1 = 0.0f;

    const int n0 = iBase + 16 * wid + (lane >> 2);
    const uint32_t eb0 = ((uint32_t)h << 24) | ((uint32_t)n0 << 12);
    const uint32_t eb1 = eb0 + (8u << 12);
    const float C = 0.18033688011112042f;   // 0.125 * log2(e)
    const int qrow = 16 * wid + (lane & 15);
    const int qcsel = (lane >> 4) << 3;

    for (int t = 0; t < 64; t++) {
        const int j0 = t * 64;

        __syncthreads();   // previous tile's K/V reads done (and Q staging at t=0)

        // ---- stage K (hi/lo) and V (plain fp16) into smem ----
#pragma unroll
        for (int it = 0; it < 4; it++) {
            int pos = tid + it * 256;
            int row = pos >> 4;
            int c4 = pos & 15;
            size_t goff = (size_t)(j0 + row) * 1024 + h * 64 + c4 * 4;
            float4 kg = *reinterpret_cast<const float4*>(k + goff);
            float4 vg = *reinterpret_cast<const float4*>(v + goff);
            int idx = swz(row, c4 * 4);
            uint32_t h0, l0, h1, l1;
            cvt_hilo(kg.x, kg.y, h0, l0);
            cvt_hilo(kg.z, kg.w, h1, l1);
            *reinterpret_cast<uint2*>(&Khi[idx]) = make_uint2(h0, h1);
            *reinterpret_cast<uint2*>(&Klo[idx]) = make_uint2(l0, l1);
            *reinterpret_cast<uint2*>(&Vs[idx]) =
                make_uint2(cvt_h2(vg.x, vg.y), cvt_h2(vg.z, vg.w));
        }
        __syncthreads();

        // ---- dropout masks: 32 independent threefry chains, batched for ILP ----
        uint32_t mask = 0;
#pragma unroll
        for (int nt = 0; nt < 8; nt++) {
            uint32_t jb = (uint32_t)(j0 + 8 * nt + 2 * qd);
            mask |= keep_mask(eb0 + jb)      << (4 * nt);
            mask |= keep_mask(eb0 + jb + 1u) << (4 * nt + 1);
            mask |= keep_mask(eb1 + jb)      << (4 * nt + 2);
            mask |= keep_mask(eb1 + jb + 1u) << (4 * nt + 3);
        }

        // ---- MMA1: S = Q K^T (split fp16: qh*kh + qh*kl + ql*kh) ----
        float s[8][4];
#pragma unroll
        for (int nt = 0; nt < 8; nt++)
#pragma unroll
            for (int c = 0; c < 4; c++) s[nt][c] = 0.0f;

#pragma unroll
        for (int kp = 0; kp < 2; kp++) {
            uint32_t qh0[4], qh1[4], ql0[4], ql1[4];
            int c0 = (2 * kp) * 16 + qcsel;
            int c1 = (2 * kp + 1) * 16 + qcsel;
            ldsm4(qh0[0], qh0[1], qh0[2], qh0[3], sptr(&SH[SQHI + swz(qrow, c0)]));
            ldsm4(qh1[0], qh1[1], qh1[2], qh1[3], sptr(&SH[SQHI + swz(qrow, c1)]));
            ldsm4(ql0[0], ql0[1], ql0[2], ql0[3], sptr(&SH[SQLO + swz(qrow, c0)]));
            ldsm4(ql1[0], ql1[1], ql1[2], ql1[3], sptr(&SH[SQLO + swz(qrow, c1)]));
#pragma unroll
            for (int nt = 0; nt < 8; nt++) {
                int brow = 8 * nt + (lane & 7);
                int bcol = 32 * kp + (lane & 24);
                uint32_t bh0, bh1, bh2, bh3, bl0, bl1, bl2, bl3;
                ldsm4(bh0, bh1, bh2, bh3, sptr(&Khi[swz(brow, bcol)]));
                ldsm4(bl0, bl1, bl2, bl3, sptr(&Klo[swz(brow, bcol)]));
                mma16816(s[nt], qh0, bh0, bh1);
                mma16816(s[nt], qh0, bl0, bl1);
                mma16816(s[nt], ql0, bh0, bh1);
                mma16816(s[nt], qh1, bh2, bh3);
                mma16816(s[nt], qh1, bl2, bl3);
                mma16816(s[nt], ql1, bh2, bh3);
            }
        }

        // ---- epilogue: exp, apply mask bits, pack P to plain fp16 A-frags ----
        uint32_t ah[4][4];
#pragma unroll
        for (int nt = 0; nt < 8; nt++) {
            float p00 = ex2(s[nt][0] * C);
            float p01 = ex2(s[nt][1] * C);
            float p10 = ex2(s[nt][2] * C);
            float p11 = ex2(s[nt][3] * C);
            lp0 += p00 + p01;
            lp1 += p10 + p11;
            if (!((mask >> (4 * nt)) & 1u))     p00 = 0.0f;
            if (!((mask >> (4 * nt + 1)) & 1u)) p01 = 0.0f;
            if (!((mask >> (4 * nt + 2)) & 1u)) p10 = 0.0f;
            if (!((mask >> (4 * nt + 3)) & 1u)) p11 = 0.0f;
            int kk2 = nt >> 1, sel = (nt & 1) * 2;
            ah[kk2][sel + 0] = cvt_h2(p00, p01);
            ah[kk2][sel + 1] = cvt_h2(p10, p11);
        }

        // ---- MMA2: O += P V (both plain fp16) ----
#pragma unroll
        for (int nt = 0; nt < 8; nt++) {
            int bcol = 8 * nt;
#pragma unroll
            for (int kp = 0; kp < 2; kp++) {
                int brow = 32 * kp + lane;
                uint32_t vh0, vh1, vh2, vh3;
                ldsm4t(vh0, vh1, vh2, vh3, sptr(&Vs[swz(brow, bcol)]));
                mma16816(o[nt], ah[2 * kp], vh0, vh1);
                mma16816(o[nt], ah[2 * kp + 1], vh2, vh3);
            }
        }
    }

    // row-sum reduction within each quad (same row, 4 threads over columns)
    lp0 += __shfl_xor_sync(0xffffffffu, lp0, 1);
    lp0 += __shfl_xor_sync(0xffffffffu, lp0, 2);
    lp1 += __shfl_xor_sync(0xffffffffu, lp1, 1);
    lp1 += __shfl_xor_sync(0xffffffffu, lp1, 2);
    const float inv0 = 1.0f / (lp0 * 0.9f);
    const float inv1 = 1.0f / (lp1 * 0.9f);

    // scatter per reference reshape chain: out[((n&255)*16+h)*1024 + (n>>8)*64 + dv]
    const int n1 = n0 + 8;
    float* ob0 = out + (size_t)((n0 & 255) * 16 + h) * 1024 + (n0 >> 8) * 64;
    float* ob1 = out + (size_t)((n1 & 255) * 16 + h) * 1024 + (n1 >> 8) * 64;
#pragma unroll
    for (int nt = 0; nt < 8; nt++) {
        int dv = 8 * nt + 2 * qd;
        *reinterpret_cast<float2*>(ob0 + dv) = make_float2(o[nt][0] * inv0, o[nt][1] * inv0);
        *reinterpret_cast<float2*>(ob1 + dv) = make_float2(o[nt][2] * inv1, o[nt][3] * inv1);
    }
}

extern "C" void kernel_launch(void* const* d_in, const int* in_sizes, int n_in,
                              void* d_out, int out_size)
{
    const float* q = (const float*)d_in[0];
    const float* k = (const float*)d_in[1];
    const float* v = (const float*)d_in[2];
    float* out = (float*)d_out;
    cudaFuncSetAttribute(attn_mma, cudaFuncAttributeMaxDynamicSharedMemorySize, SMEM_BYTES);
    dim3 grid(NSEQ / 128, NHEAD);
    attn_mma<<<grid, 256, SMEM_BYTES>>>(q, k, v, out);
}

// round 16
// speedup vs baseline: 1.7837x; 1.2888x over previous
#include <cuda_runtime.h>
#include <cuda_fp16.h>
#include <cstdint>

// R16 = R15 with QK^T in PLAIN fp16 (Qlo/Klo planes deleted): MMA1 96->32 HMMA.
// All operands plain fp16 now; error budget ~4.5e-4 (measured components).
// 2 CTAs/SM, single-buffer K/V, 2 syncs/tile, batched threefry masks.
// B=1, S=4096, H=16, D=64. BM=128 (8 warps x 16 rows), BN=64 keys/tile.

#define NSEQ 4096
#define NHEAD 16

// half-element offsets in dynamic smem (32KB total)
#define SQ 0
#define SK 8192
#define SV 12288
#define SMEM_BYTES (16384 * 2)

// ---------------- threefry2x32, key (0,42), draw = bits1 ^ bits2 ----------------
__device__ __forceinline__ void tf_g0(uint32_t& a, uint32_t& b) {
    a += b; b = __funnelshift_l(b, b, 13); b ^= a;
    a += b; b = __funnelshift_l(b, b, 15); b ^= a;
    a += b; b = __funnelshift_l(b, b, 26); b ^= a;
    a += b; b = __funnelshift_l(b, b, 6);  b ^= a;
}
__device__ __forceinline__ void tf_g1(uint32_t& a, uint32_t& b) {
    a += b; b = __funnelshift_l(b, b, 17); b ^= a;
    a += b; b = __funnelshift_l(b, b, 29); b ^= a;
    a += b; b = __funnelshift_l(b, b, 16); b ^= a;
    a += b; b = __funnelshift_l(b, b, 24); b ^= a;
}
__device__ __forceinline__ uint32_t keep_mask(uint32_t e) {
    uint32_t a = 0u;
    uint32_t b = e + 42u;
    tf_g0(a, b); a += 42u;          b += 0x1BD11BF1u;
    tf_g1(a, b); a += 0x1BD11BF0u;  b += 2u;
    tf_g0(a, b);                    b += 45u;
    tf_g1(a, b); a += 42u;          b += 0x1BD11BF4u;
    tf_g0(a, b); a += 0x1BD11BF0u;  b += 5u;
    // (x>>9) < 7549747  <=>  x < 7549747*512 (bit-exact, saves the SHF)
    return ((a ^ b) < 3865470464u) ? 1u : 0u;
}

// ---------------- smem swizzle: 64-half rows (128B), XOR 16B-chunk swizzle ----------------
__device__ __forceinline__ int swz(int row, int col) {
    return (row << 6) + ((((col >> 3) ^ (row & 7)) << 3) | (col & 7));
}
__device__ __forceinline__ uint32_t sptr(const void* p) {
    return (uint32_t)__cvta_generic_to_shared(p);
}
__device__ __forceinline__ void ldsm4(uint32_t& r0, uint32_t& r1, uint32_t& r2, uint32_t& r3, uint32_t a) {
    asm volatile("ldmatrix.sync.aligned.m8n8.x4.shared.b16 {%0,%1,%2,%3}, [%4];"
                 : "=r"(r0), "=r"(r1), "=r"(r2), "=r"(r3) : "r"(a));
}
__device__ __forceinline__ void ldsm4t(uint32_t& r0, uint32_t& r1, uint32_t& r2, uint32_t& r3, uint32_t a) {
    asm volatile("ldmatrix.sync.aligned.m8n8.x4.trans.shared.b16 {%0,%1,%2,%3}, [%4];"
                 : "=r"(r0), "=r"(r1), "=r"(r2), "=r"(r3) : "r"(a));
}
__device__ __forceinline__ void mma16816(float* c, const uint32_t* a, uint32_t b0, uint32_t b1) {
    asm volatile(
        "mma.sync.aligned.m16n8k16.row.col.f32.f16.f16.f32 "
        "{%0,%1,%2,%3},{%4,%5,%6,%7},{%8,%9},{%0,%1,%2,%3};"
        : "+f"(c[0]), "+f"(c[1]), "+f"(c[2]), "+f"(c[3])
        : "r"(a[0]), "r"(a[1]), "r"(a[2]), "r"(a[3]), "r"(b0), "r"(b1));
}
__device__ __forceinline__ uint32_t cvt_h2(float x, float y) {
    __half2 h = __floats2half2_rn(x, y);
    return *reinterpret_cast<uint32_t*>(&h);
}
__device__ __forceinline__ float ex2(float x) {
    float y;
    asm("ex2.approx.ftz.f32 %0, %1;" : "=f"(y) : "f"(x));
    return y;
}

__global__ void __launch_bounds__(256, 2)
attn_mma(const float* __restrict__ q, const float* __restrict__ k,
         const float* __restrict__ v, float* __restrict__ out)
{
    extern __shared__ __align__(16) __half SH[];
    __half* Ks = SH + SK;
    __half* Vs = SH + SV;

    const int tid = threadIdx.x;
    const int wid = tid >> 5;
    const int lane = tid & 31;
    const int qd = lane & 3;
    const int h = blockIdx.y;
    const int iBase = blockIdx.x * 128;

    // ---- stage Q (fp32 -> plain fp16) into dedicated smem (persistent) ----
#pragma unroll
    for (int it = 0; it < 8; it++) {
        int pos = tid + it * 256;          // 0..2047 float4s
        int row = pos >> 4;                // 0..127
        int c4 = pos & 15;
        float4 g = *reinterpret_cast<const float4*>(q + (size_t)(iBase + row) * 1024 + h * 64 + c4 * 4);
        int idx = swz(row, c4 * 4);
        *reinterpret_cast<uint2*>(&SH[SQ + idx]) =
            make_uint2(cvt_h2(g.x, g.y), cvt_h2(g.z, g.w));
    }

    float o[8][4];
#pragma unroll
    for (int nt = 0; nt < 8; nt++)
#pragma unroll
        for (int c = 0; c < 4; c++) o[nt][c] = 0.0f;
    float lp0 = 0.0f, lp1 = 0.0f;

    const int n0 = iBase + 16 * wid + (lane >> 2);
    const uint32_t eb0 = ((uint32_t)h << 24) | ((uint32_t)n0 << 12);
    const uint32_t eb1 = eb0 + (8u << 12);
    const float C = 0.18033688011112042f;   // 0.125 * log2(e)
    const int qrow = 16 * wid + (lane & 15);
    const int qcsel = (lane >> 4) << 3;

    for (int t = 0; t < 64; t++) {
        const int j0 = t * 64;

        __syncthreads();   // previous tile's K/V reads done (and Q staging at t=0)

        // ---- stage K and V (plain fp16) into smem ----
#pragma unroll
        for (int it = 0; it < 4; it++) {
            int pos = tid + it * 256;
            int row = pos >> 4;
            int c4 = pos & 15;
            size_t goff = (size_t)(j0 + row) * 1024 + h * 64 + c4 * 4;
            float4 kg = *reinterpret_cast<const float4*>(k + goff);
            float4 vg = *reinterpret_cast<const float4*>(v + goff);
            int idx = swz(row, c4 * 4);
            *reinterpret_cast<uint2*>(&Ks[idx]) =
                make_uint2(cvt_h2(kg.x, kg.y), cvt_h2(kg.z, kg.w));
            *reinterpret_cast<uint2*>(&Vs[idx]) =
                make_uint2(cvt_h2(vg.x, vg.y), cvt_h2(vg.z, vg.w));
        }
        __syncthreads();

        // ---- dropout masks: 32 independent threefry chains, batched for ILP ----
        uint32_t mask = 0;
#pragma unroll
        for (int nt = 0; nt < 8; nt++) {
            uint32_t jb = (uint32_t)(j0 + 8 * nt + 2 * qd);
            mask |= keep_mask(eb0 + jb)      << (4 * nt);
            mask |= keep_mask(eb0 + jb + 1u) << (4 * nt + 1);
            mask |= keep_mask(eb1 + jb)      << (4 * nt + 2);
            mask |= keep_mask(eb1 + jb + 1u) << (4 * nt + 3);
        }

        // ---- MMA1: S = Q K^T (plain fp16) ----
        float s[8][4];
#pragma unroll
        for (int nt = 0; nt < 8; nt++)
#pragma unroll
            for (int c = 0; c < 4; c++) s[nt][c] = 0.0f;

#pragma unroll
        for (int kp = 0; kp < 2; kp++) {
            uint32_t qh0[4], qh1[4];
            int c0 = (2 * kp) * 16 + qcsel;
            int c1 = (2 * kp + 1) * 16 + qcsel;
            ldsm4(qh0[0], qh0[1], qh0[2], qh0[3], sptr(&SH[SQ + swz(qrow, c0)]));
            ldsm4(qh1[0], qh1[1], qh1[2], qh1[3], sptr(&SH[SQ + swz(qrow, c1)]));
#pragma unroll
            for (int nt = 0; nt < 8; nt++) {
                int brow = 8 * nt + (lane & 7);
                int bcol = 32 * kp + (lane & 24);
                uint32_t bh0, bh1, bh2, bh3;
                ldsm4(bh0, bh1, bh2, bh3, sptr(&Ks[swz(brow, bcol)]));
                mma16816(s[nt], qh0, bh0, bh1);
                mma16816(s[nt], qh1, bh2, bh3);
            }
        }

        // ---- epilogue: exp, apply mask bits, pack P to plain fp16 A-frags ----
        uint32_t ah[4][4];
#pragma unroll
        for (int nt = 0; nt < 8; nt++) {
            float p00 = ex2(s[nt][0] * C);
            float p01 = ex2(s[nt][1] * C);
            float p10 = ex2(s[nt][2] * C);
            float p11 = ex2(s[nt][3] * C);
            lp0 += p00 + p01;
            lp1 += p10 + p11;
            if (!((mask >> (4 * nt)) & 1u))     p00 = 0.0f;
            if (!((mask >> (4 * nt + 1)) & 1u)) p01 = 0.0f;
            if (!((mask >> (4 * nt + 2)) & 1u)) p10 = 0.0f;
            if (!((mask >> (4 * nt + 3)) & 1u)) p11 = 0.0f;
            int kk2 = nt >> 1, sel = (nt & 1) * 2;
            ah[kk2][sel + 0] = cvt_h2(p00, p01);
            ah[kk2][sel + 1] = cvt_h2(p10, p11);
        }

        // ---- MMA2: O += P V (both plain fp16) ----
#pragma unroll
        for (int nt = 0; nt < 8; nt++) {
            int bcol = 8 * nt;
#pragma unroll
            for (int kp = 0; kp < 2; kp++) {
                int brow = 32 * kp + lane;
                uint32_t vh0, vh1, vh2, vh3;
                ldsm4t(vh0, vh1, vh2, vh3, sptr(&Vs[swz(brow, bcol)]));
                mma16816(o[nt], ah[2 * kp], vh0, vh1);
                mma16816(o[nt], ah[2 * kp + 1], vh2, vh3);
            }
        }
    }

    // row-sum reduction within each quad (same row, 4 threads over columns)
    lp0 += __shfl_xor_sync(0xffffffffu, lp0, 1);
    lp0 += __shfl_xor_sync(0xffffffffu, lp0, 2);
    lp1 += __shfl_xor_sync(0xffffffffu, lp1, 1);
    lp1 += __shfl_xor_sync(0xffffffffu, lp1, 2);
    const float inv0 = 1.0f / (lp0 * 0.9f);
    const float inv1 = 1.0f / (lp1 * 0.9f);

    // scatter per reference reshape chain: out[((n&255)*16+h)*1024 + (n>>8)*64 + dv]
    const int n1 = n0 + 8;
    float* ob0 = out + (size_t)((n0 & 255) * 16 + h) * 1024 + (n0 >> 8) * 64;
    float* ob1 = out + (size_t)((n1 & 255) * 16 + h) * 1024 + (n1 >> 8) * 64;
#pragma unroll
    for (int nt = 0; nt < 8; nt++) {
        int dv = 8 * nt + 2 * qd;
        *reinterpret_cast<float2*>(ob0 + dv) = make_float2(o[nt][0] * inv0, o[nt][1] * inv0);
        *reinterpret_cast<float2*>(ob1 + dv) = make_float2(o[nt][2] * inv1, o[nt][3] * inv1);
    }
}

extern "C" void kernel_launch(void* const* d_in, const int* in_sizes, int n_in,
                              void* d_out, int out_size)
{
    const float* q = (const float*)d_in[0];
    const float* k = (const float*)d_in[1];
    const float* v = (const float*)d_in[2];
    float* out = (float*)d_out;
    cudaFuncSetAttribute(attn_mma, cudaFuncAttributeMaxDynamicSharedMemorySize, SMEM_BYTES);
    dim3 grid(NSEQ / 128, NHEAD);
    attn_mma<<<grid, 256, SMEM_BYTES>>>(q, k, v, out);
}